// round 5
// baseline (speedup 1.0000x reference)
#include <cuda_runtime.h>

// Rotated-BEV IoU loss — single persistent kernel, 4 phases with grid barriers.
// d_in[0] iou_pred (N,1) f32, d_in[1] box_pred (N,7) f32,
// d_in[2] box_gt (M,7) f32, d_in[3] num_total_pos (int32 scalar, optional)
// d_out: scalar f32

#define EPSF 1e-8f
#define MAXB 8192
#define PAIR_CAP 131072
#define GBLOCK 256

__device__ float4 d_bb[MAXB];        // cx, cy, ex, ey (AABB half-extents)
__device__ float  d_area[MAXB];
__device__ float  d_crn[MAXB * 8];   // corners x0,y0..x3,y3 CCW
__device__ int    g_rowmax[MAXB];    // float bits of row max IoU (>=0)
__device__ int    g_pairs[PAIR_CAP]; // packed (row<<16)|j
__device__ int    g_paircnt = 0;
__device__ int    g_bar_cnt = 0;
__device__ int    g_bar_gen = 0;     // monotonic across replays — no reset needed

// ---------------------------------------------------------------------------
__device__ __forceinline__ void grid_barrier(int nblocks)
{
    __syncthreads();
    if (threadIdx.x == 0) {
        const int gen = atomicAdd(&g_bar_gen, 0);
        __threadfence();
        if (atomicAdd(&g_bar_cnt, 1) == nblocks - 1) {
            atomicExch(&g_bar_cnt, 0);
            __threadfence();
            atomicAdd(&g_bar_gen, 1);
        } else {
            while (atomicAdd(&g_bar_gen, 0) == gen) __nanosleep(32);
        }
        __threadfence();
    }
    __syncthreads();
}

// ---------------------------------------------------------------------------
// Intersection area of two convex CCW quads (x0,y0,...,x3,y3).
__device__ float quad_inter_area(const float* __restrict__ A,
                                 const float* __restrict__ B)
{
    float px[8], py[8], qx[8], qy[8];
    int n = 4;
#pragma unroll
    for (int k = 0; k < 4; ++k) { px[k] = A[2 * k]; py[k] = A[2 * k + 1]; }

#pragma unroll
    for (int e = 0; e < 4; ++e) {
        const float p1x = B[2 * e], p1y = B[2 * e + 1];
        const int e2 = ((e + 1) & 3) * 2;
        const float ex = B[e2] - p1x, ey = B[e2 + 1] - p1y;
        int m = 0;
        float xprev = px[n - 1], yprev = py[n - 1];
        float dprev = ex * (yprev - p1y) - ey * (xprev - p1x);
        for (int k = 0; k < n; ++k) {
            const float xc = px[k], yc = py[k];
            const float dc = ex * (yc - p1y) - ey * (xc - p1x);
            if ((dc >= 0.0f) != (dprev >= 0.0f)) {
                const float t = dprev / (dprev - dc);
                qx[m] = fmaf(t, xc - xprev, xprev);
                qy[m] = fmaf(t, yc - yprev, yprev);
                ++m;
            }
            if (dc >= 0.0f) { qx[m] = xc; qy[m] = yc; ++m; }
            xprev = xc; yprev = yc; dprev = dc;
        }
        n = m;
        if (n == 0) return 0.0f;
        for (int k = 0; k < n; ++k) { px[k] = qx[k]; py[k] = qy[k]; }
    }
    if (n < 3) return 0.0f;
    float s = 0.0f;
    float xp = px[n - 1], yp = py[n - 1];
    for (int k = 0; k < n; ++k) {
        s += xp * py[k] - px[k] * yp;
        xp = px[k]; yp = py[k];
    }
    return 0.5f * fabsf(s);
}

// ---------------------------------------------------------------------------
__global__ void __launch_bounds__(GBLOCK, 4)
fused_kernel(const float* __restrict__ iou_pred,
             const float* __restrict__ box_pred,
             const float* __restrict__ box_gt,
             float* __restrict__ out,
             const int* __restrict__ ntp_ptr, int has_ntp,
             int N, int M, int nblocks)
{
    const int tid = threadIdx.x;
    const int gtid = blockIdx.x * GBLOCK + tid;
    const int gthreads = nblocks * GBLOCK;
    const int lane = tid & 31;

    // ---- Phase A: prep ----
    for (int i = gtid; i < N + M; i += gthreads) {
        if (i < N) g_rowmax[i] = 0;
        const float* b = (i < N) ? (box_pred + (size_t)i * 7)
                                 : (box_gt + (size_t)(i - N) * 7);
        const float x = b[0], y = b[1], dx = b[3], dy = b[4], yaw = b[6];
        float s, c;
        __sincosf(yaw, &s, &c);
        const float hx = 0.5f * dx, hy = 0.5f * dy;
        float* cr = d_crn + (size_t)i * 8;
        cr[0] = x + c * hx - s * hy;  cr[1] = y + s * hx + c * hy;
        cr[2] = x - c * hx - s * hy;  cr[3] = y - s * hx + c * hy;
        cr[4] = x - c * hx + s * hy;  cr[5] = y - s * hx - c * hy;
        cr[6] = x + c * hx + s * hy;  cr[7] = y + s * hx - c * hy;
        const float ac = fabsf(c), as = fabsf(s);
        d_bb[i] = make_float4(x, y, hx * ac + hy * as + 1e-4f,
                                    hx * as + hy * ac + 1e-4f);
        d_area[i] = dx * dy;
    }

    grid_barrier(nblocks);

    // ---- Phase B: AABB pair test + warp-aggregated survivor push ----
    {
        const int total = N * M;
        for (int p = gtid; p < total; p += gthreads) {
            const int row = p / M;
            const int j = p - row * M;
            const float4 a = d_bb[row];
            const float4 b = d_bb[N + j];
            const bool pass = (fabsf(a.x - b.x) <= a.z + b.z) &
                              (fabsf(a.y - b.y) <= a.w + b.w);
            const unsigned m = __ballot_sync(0xFFFFFFFFu, pass);
            if (m) {
                const int leader = __ffs(m) - 1;
                int base = 0;
                if (lane == leader) base = atomicAdd(&g_paircnt, __popc(m));
                base = __shfl_sync(0xFFFFFFFFu, base, leader);
                if (pass) {
                    const int idx = base + __popc(m & ((1u << lane) - 1u));
                    if (idx < PAIR_CAP) g_pairs[idx] = (row << 16) | j;
                }
            }
        }
    }

    grid_barrier(nblocks);

    // ---- Phase C: clip survivors ----
    {
        const int cnt = min(g_paircnt, PAIR_CAP);
        for (int i = gtid; i < cnt; i += gthreads) {
            const int packed = g_pairs[i];
            const int row = packed >> 16;
            const int j = packed & 0xFFFF;
            float A[8], B[8];
            const float4* pa = (const float4*)(d_crn + (size_t)row * 8);
            const float4* pb = (const float4*)(d_crn + (size_t)(N + j) * 8);
            const float4 a0 = pa[0], a1 = pa[1], b0 = pb[0], b1 = pb[1];
            A[0] = a0.x; A[1] = a0.y; A[2] = a0.z; A[3] = a0.w;
            A[4] = a1.x; A[5] = a1.y; A[6] = a1.z; A[7] = a1.w;
            B[0] = b0.x; B[1] = b0.y; B[2] = b0.z; B[3] = b0.w;
            B[4] = b1.x; B[5] = b1.y; B[6] = b1.z; B[7] = b1.w;
            const float inter = quad_inter_area(A, B);
            if (inter > 0.0f) {
                const float uni = fmaxf(d_area[row] + d_area[N + j] - inter, EPSF);
                atomicMax(&g_rowmax[row], __float_as_int(inter / uni));
            }
        }
    }

    grid_barrier(nblocks);

    // ---- Phase D: block 0 does the deterministic final reduction ----
    if (blockIdx.x != 0) return;

    float s = 0.0f;
    for (int i = tid; i < N; i += GBLOCK) {
        const float mx = __int_as_float(g_rowmax[i]);
        s += fabsf(iou_pred[i] - (2.0f * mx - 1.0f));
    }
#pragma unroll
    for (int o = 16; o > 0; o >>= 1)
        s += __shfl_down_sync(0xFFFFFFFFu, s, o);

    __shared__ float wsum[GBLOCK / 32];
    if (lane == 0) wsum[tid >> 5] = s;
    __syncthreads();
    if (tid == 0) {
        float tot = 0.0f;
#pragma unroll
        for (int w = 0; w < GBLOCK / 32; ++w) tot += wsum[w];
        float ntp = 2048.0f;
        if (has_ntp) {
            const int iv = *ntp_ptr;
            if (iv > 0 && iv < 100000000) ntp = (float)iv;
            else ntp = __int_as_float(iv);
        }
        out[0] = tot / (ntp + 1e-4f);
        g_paircnt = 0;   // reset for next graph replay
    }
}

// ---------------------------------------------------------------------------
extern "C" void kernel_launch(void* const* d_in, const int* in_sizes, int n_in,
                              void* d_out, int out_size)
{
    const float* iou_pred = (const float*)d_in[0];
    const float* box_pred = (const float*)d_in[1];
    const float* box_gt   = (const float*)d_in[2];
    const int N = in_sizes[1] / 7;
    const int M = in_sizes[2] / 7;
    const int* ntp_ptr = (n_in >= 4) ? (const int*)d_in[3] : nullptr;
    const int has_ntp = (n_in >= 4) ? 1 : 0;

    int sms = 0;
    cudaDeviceGetAttribute(&sms, cudaDevAttrMultiProcessorCount, 0);
    if (sms <= 0) sms = 148;
    const int nblocks = sms * 4;   // guaranteed co-resident via __launch_bounds__(256,4)

    fused_kernel<<<nblocks, GBLOCK>>>(iou_pred, box_pred, box_gt, (float*)d_out,
                                      ntp_ptr, has_ntp, N, M, nblocks);
}

// round 7
// speedup vs baseline: 1.8448x; 1.8448x over previous
#include <cuda_runtime.h>

// Rotated-BEV IoU loss — ONE kernel, block-owns-rows, no grid barriers.
// d_in[0] iou_pred (N,1) f32, d_in[1] box_pred (N,7) f32,
// d_in[2] box_gt (M,7) f32, d_in[3] num_total_pos (int32 scalar, optional)
// d_out: scalar f32

#define EPSF 1e-8f
#define MAXN 8192
#define ROWS_PB 8
#define GTILE 512
#define BLOCK 256

__device__ float g_row[MAXN];   // per-row |iou_pred - target|
__device__ int   g_done = 0;    // last-block counter (reset by reducer)

// ---------------------------------------------------------------------------
// Intersection area of two convex CCW quads (x0,y0,...,x3,y3).
__device__ float quad_inter_area(const float* __restrict__ A,
                                 const float* __restrict__ B)
{
    float px[8], py[8], qx[8], qy[8];
    int n = 4;
#pragma unroll
    for (int k = 0; k < 4; ++k) { px[k] = A[2 * k]; py[k] = A[2 * k + 1]; }

#pragma unroll
    for (int e = 0; e < 4; ++e) {
        const float p1x = B[2 * e], p1y = B[2 * e + 1];
        const int e2 = ((e + 1) & 3) * 2;
        const float ex = B[e2] - p1x, ey = B[e2 + 1] - p1y;
        int m = 0;
        float xprev = px[n - 1], yprev = py[n - 1];
        float dprev = ex * (yprev - p1y) - ey * (xprev - p1x);
        for (int k = 0; k < n; ++k) {
            const float xc = px[k], yc = py[k];
            const float dc = ex * (yc - p1y) - ey * (xc - p1x);
            if ((dc >= 0.0f) != (dprev >= 0.0f)) {
                const float t = dprev / (dprev - dc);
                qx[m] = fmaf(t, xc - xprev, xprev);
                qy[m] = fmaf(t, yc - yprev, yprev);
                ++m;
            }
            if (dc >= 0.0f) { qx[m] = xc; qy[m] = yc; ++m; }
            xprev = xc; yprev = yc; dprev = dc;
        }
        n = m;
        if (n == 0) return 0.0f;
        for (int k = 0; k < n; ++k) { px[k] = qx[k]; py[k] = qy[k]; }
    }
    if (n < 3) return 0.0f;
    float s = 0.0f;
    float xp = px[n - 1], yp = py[n - 1];
    for (int k = 0; k < n; ++k) {
        s += xp * py[k] - px[k] * yp;
        xp = px[k]; yp = py[k];
    }
    return 0.5f * fabsf(s);
}

// ---------------------------------------------------------------------------
__global__ void __launch_bounds__(BLOCK)
fused_kernel(const float* __restrict__ iou_pred,
             const float* __restrict__ box_pred,
             const float* __restrict__ box_gt,
             float* __restrict__ out,
             const int* __restrict__ ntp_ptr, int has_ntp,
             int N, int M)
{
    // gt tile
    __shared__ float sgx[GTILE], sgy[GTILE], sgex[GTILE], sgey[GTILE];
    __shared__ float sghx[GTILE], sghy[GTILE], sgc[GTILE], sgs[GTILE];
    // pred rows (block-exclusive)
    __shared__ float prx[ROWS_PB], pry[ROWS_PB], prex[ROWS_PB], prey[ROWS_PB];
    __shared__ float parea[ROWS_PB];
    __shared__ float pcrn[ROWS_PB][8];
    __shared__ int   rowmaxbits[ROWS_PB];
    __shared__ int   scnt;
    __shared__ int   slist[ROWS_PB * GTILE];   // cap == worst case, no overflow

    const int tid = threadIdx.x;
    const int lane = tid & 31;
    const int row0 = blockIdx.x * ROWS_PB;
    const int nrows = min(ROWS_PB, N - row0);

    // ---- pred-row prep (threads 0..ROWS_PB-1) ----
    if (tid < ROWS_PB) {
        rowmaxbits[tid] = 0;
        const int row = row0 + tid;
        if (row < N) {
            const float* b = box_pred + (size_t)row * 7;
            const float x = b[0], y = b[1];
            const float hx = 0.5f * b[3], hy = 0.5f * b[4];
            float s, c;
            __sincosf(b[6], &s, &c);
            prx[tid] = x; pry[tid] = y;
            prex[tid] = hx * fabsf(c) + hy * fabsf(s) + 1e-4f;
            prey[tid] = hx * fabsf(s) + hy * fabsf(c) + 1e-4f;
            parea[tid] = b[3] * b[4];
            pcrn[tid][0] = x + c * hx - s * hy;  pcrn[tid][1] = y + s * hx + c * hy;
            pcrn[tid][2] = x - c * hx - s * hy;  pcrn[tid][3] = y - s * hx + c * hy;
            pcrn[tid][4] = x - c * hx + s * hy;  pcrn[tid][5] = y - s * hx - c * hy;
            pcrn[tid][6] = x + c * hx + s * hy;  pcrn[tid][7] = y + s * hx - c * hy;
        }
    }
    if (tid == 0) scnt = 0;

    // ---- tiles over gt boxes (single tile when M <= GTILE) ----
    for (int jt = 0; jt < M; jt += GTILE) {
        const int csz = min(GTILE, M - jt);
        __syncthreads();
        // stage gt chunk (compute extents/rotation on the fly — no prep kernel)
        for (int j = tid; j < csz; j += BLOCK) {
            const float* b = box_gt + (size_t)(jt + j) * 7;
            const float x = b[0], y = b[1];
            const float hx = 0.5f * b[3], hy = 0.5f * b[4];
            float s, c;
            __sincosf(b[6], &s, &c);
            sgx[j] = x; sgy[j] = y;
            sgex[j] = hx * fabsf(c) + hy * fabsf(s) + 1e-4f;
            sgey[j] = hx * fabsf(s) + hy * fabsf(c) + 1e-4f;
            sghx[j] = hx; sghy[j] = hy; sgc[j] = c; sgs[j] = s;
        }
        __syncthreads();

        // test: ROWS_PB rows x csz gt (uniform trip count for all threads)
        const int ntrips = (csz + BLOCK - 1) / BLOCK;
        for (int t = 0; t < ntrips; ++t) {
            const int j = t * BLOCK + tid;
            const bool jvalid = (j < csz);
            float gxv = 0.f, gyv = 0.f, gexv = -1e30f, geyv = -1e30f;
            if (jvalid) { gxv = sgx[j]; gyv = sgy[j]; gexv = sgex[j]; geyv = sgey[j]; }
            for (int r = 0; r < nrows; ++r) {
                const bool pass = jvalid &
                    (fabsf(prx[r] - gxv) <= prex[r] + gexv) &
                    (fabsf(pry[r] - gyv) <= prey[r] + geyv);
                const unsigned msk = __ballot_sync(0xFFFFFFFFu, pass);
                if (msk) {
                    const int leader = __ffs(msk) - 1;
                    int base = 0;
                    if (lane == leader) base = atomicAdd(&scnt, __popc(msk));
                    base = __shfl_sync(0xFFFFFFFFu, base, leader);
                    if (pass)
                        slist[base + __popc(msk & ((1u << lane) - 1u))] = (r << 16) | j;
                }
            }
        }
        __syncthreads();

        // clip survivors of this tile in parallel
        const int cnt = scnt;
        for (int i = tid; i < cnt; i += BLOCK) {
            const int pk = slist[i];
            const int r = pk >> 16;
            const int jj = pk & 0xFFFF;
            float A[8], B[8];
#pragma unroll
            for (int k = 0; k < 8; ++k) A[k] = pcrn[r][k];
            const float x = sgx[jj], y = sgy[jj];
            const float hx = sghx[jj], hy = sghy[jj];
            const float c = sgc[jj], s = sgs[jj];
            B[0] = x + c * hx - s * hy;  B[1] = y + s * hx + c * hy;
            B[2] = x - c * hx - s * hy;  B[3] = y - s * hx + c * hy;
            B[4] = x - c * hx + s * hy;  B[5] = y - s * hx - c * hy;
            B[6] = x + c * hx + s * hy;  B[7] = y + s * hx - c * hy;
            const float inter = quad_inter_area(A, B);
            if (inter > 0.0f) {
                const float uni = fmaxf(parea[r] + 4.0f * hx * hy - inter, EPSF);
                atomicMax(&rowmaxbits[r], __float_as_int(inter / uni));
            }
        }
        __syncthreads();
        if (tid == 0) scnt = 0;
    }
    __syncthreads();

    if (tid < nrows) {
        const int row = row0 + tid;
        const float mx = __int_as_float(rowmaxbits[tid]);
        g_row[row] = fabsf(iou_pred[row] - (2.0f * mx - 1.0f));
    }

    // ---- last finished block does the deterministic final reduction ----
    __shared__ int isLast;
    if (tid == 0) {
        __threadfence();
        isLast = (atomicAdd(&g_done, 1) == (int)gridDim.x - 1);
    }
    __syncthreads();
    if (!isLast) return;
    __threadfence();

    float sum = 0.0f;
    for (int i = tid; i < N; i += BLOCK) sum += g_row[i];
#pragma unroll
    for (int o = 16; o > 0; o >>= 1)
        sum += __shfl_down_sync(0xFFFFFFFFu, sum, o);

    __shared__ float wsum[BLOCK / 32];
    if (lane == 0) wsum[tid >> 5] = sum;
    __syncthreads();
    if (tid == 0) {
        float tot = 0.0f;
#pragma unroll
        for (int w = 0; w < BLOCK / 32; ++w) tot += wsum[w];
        float ntp = 2048.0f;
        if (has_ntp) {
            const int iv = *ntp_ptr;
            if (iv > 0 && iv < 100000000) ntp = (float)iv;
            else ntp = __int_as_float(iv);
        }
        out[0] = tot / (ntp + 1e-4f);
        g_done = 0;   // reset for next graph replay
    }
}

// ---------------------------------------------------------------------------
extern "C" void kernel_launch(void* const* d_in, const int* in_sizes, int n_in,
                              void* d_out, int out_size)
{
    const float* iou_pred = (const float*)d_in[0];
    const float* box_pred = (const float*)d_in[1];
    const float* box_gt   = (const float*)d_in[2];
    const int N = in_sizes[1] / 7;
    const int M = in_sizes[2] / 7;
    const int* ntp_ptr = (n_in >= 4) ? (const int*)d_in[3] : nullptr;
    const int has_ntp = (n_in >= 4) ? 1 : 0;

    const int grid = (N + ROWS_PB - 1) / ROWS_PB;
    fused_kernel<<<grid, BLOCK>>>(iou_pred, box_pred, box_gt, (float*)d_out,
                                  ntp_ptr, has_ntp, N, M);
}